// round 5
// baseline (speedup 1.0000x reference)
#include <cuda_runtime.h>
#include <cuda_fp16.h>
#include <cstdint>

// Problem constants
#define NB    4            // batches
#define NN    2048         // n = m per batch
#define DD    256          // feature dim
#define ITERS 50
#define MU    (1.0f/2048.0f)
#define STAB  1e-8f

// ---------------- device scratch (no allocations allowed) ----------------
static __device__ __align__(128) __half g_K[2ull * NB * NN * NN];   // 67 MB: [plan][b][i][j]
static __device__ __align__(16)  __half g_fn[3][8192ull * DD];      // normalized features
static __device__ float g_u[2][NB][NN];
static __device__ float g_c[2][2][NB][NN];                          // double-buffered column sums
static __device__ float g_part[256];

__device__ __forceinline__ uint32_t smem_u32(const void* p) {
    return (uint32_t)__cvta_generic_to_shared(p);
}

// L2 evict-last policy: keep K resident across all 50 iterations.
__device__ __forceinline__ uint64_t mk_policy() {
    uint64_t p;
    asm("createpolicy.fractional.L2::evict_last.b64 %0, 1.0;" : "=l"(p));
    return p;
}
__device__ __forceinline__ uint4 ldg_el(const uint4* p, uint64_t pol) {
    uint4 r;
    asm volatile("ld.global.L2::cache_hint.v4.u32 {%0,%1,%2,%3}, [%4], %5;"
        : "=r"(r.x), "=r"(r.y), "=r"(r.z), "=r"(r.w) : "l"(p), "l"(pol));
    return r;
}
__device__ __forceinline__ void stg_el(uint32_t* p, uint32_t v, uint64_t pol) {
    asm volatile("st.global.L2::cache_hint.b32 [%0], %1, %2;"
        :: "l"(p), "r"(v), "l"(pol));
}

// ---------------- 1) row-normalize features, cast to fp16 ----------------
__global__ void __launch_bounds__(256) norm_kernel(const float* __restrict__ s0,
                                                   const float* __restrict__ s1,
                                                   const float* __restrict__ s2) {
    int gw   = (blockIdx.x * blockDim.x + threadIdx.x) >> 5;  // global warp = row id
    int lane = threadIdx.x & 31;
    int which = gw >> 13;           // 0..2
    int row   = gw & 8191;
    const float* in = which == 0 ? s0 : (which == 1 ? s1 : s2);
    const float4* p = (const float4*)(in + (size_t)row * DD);
    float4 a = p[lane];
    float4 b = p[lane + 32];
    float ss = a.x*a.x + a.y*a.y + a.z*a.z + a.w*a.w
             + b.x*b.x + b.y*b.y + b.z*b.z + b.w*b.w;
    #pragma unroll
    for (int o = 16; o; o >>= 1) ss += __shfl_xor_sync(0xffffffffu, ss, o);
    float inv = 1.0f / (sqrtf(ss) + STAB);
    __half2* out = (__half2*)&g_fn[which][(size_t)row * DD];
    out[lane*2    ] = __floats2half2_rn(a.x*inv, a.y*inv);
    out[lane*2 + 1] = __floats2half2_rn(a.z*inv, a.w*inv);
    out[64 + lane*2    ] = __floats2half2_rn(b.x*inv, b.y*inv);
    out[64 + lane*2 + 1] = __floats2half2_rn(b.z*inv, b.w*inv);
}

// ---------------- 2) K = exp(dot - 1), fp16 tensor-core GEMM ----------------
__global__ void __launch_bounds__(256) gemm_exp_kernel() {
    int z = blockIdx.z;                 // 0..7: plan*4 + b
    int plan = z >> 2, b = z & 3;
    const __half* A  = &g_fn[plan    ][(size_t)b * NN * DD];
    const __half* Bm = &g_fn[plan + 1][(size_t)b * NN * DD];
    int row0 = blockIdx.y * 128, col0 = blockIdx.x * 128;

    __shared__ __align__(16) __half sA[128 * 72];
    __shared__ __align__(16) __half sB[128 * 72];

    int tid = threadIdx.x, warp = tid >> 5, lane = tid & 31;
    int wm = warp & 1;
    int wn = warp >> 1;

    float acc[4][4][4];
    #pragma unroll
    for (int i = 0; i < 4; i++)
        #pragma unroll
        for (int j = 0; j < 4; j++)
            #pragma unroll
            for (int k = 0; k < 4; k++) acc[i][j][k] = 0.f;

    for (int kc = 0; kc < 4; kc++) {
        #pragma unroll
        for (int i = 0; i < 4; i++) {
            int idx = tid + i * 256;
            int r = idx >> 3, c8 = (idx & 7) * 8;
            *(uint4*)&sA[r*72 + c8] = *(const uint4*)&A [(size_t)(row0 + r)*DD + kc*64 + c8];
            *(uint4*)&sB[r*72 + c8] = *(const uint4*)&Bm[(size_t)(col0 + r)*DD + kc*64 + c8];
        }
        __syncthreads();
        #pragma unroll
        for (int ks = 0; ks < 4; ks++) {
            uint32_t afr[4][4], bfr[4][2];
            #pragma unroll
            for (int mt = 0; mt < 4; mt++) {
                int r = wm*64 + mt*16 + (lane & 15);
                int c = ks*16 + (lane >> 4) * 8;
                uint32_t ad = smem_u32(&sA[r*72 + c]);
                asm volatile("ldmatrix.sync.aligned.m8n8.x4.shared.b16 {%0,%1,%2,%3}, [%4];"
                    : "=r"(afr[mt][0]), "=r"(afr[mt][1]), "=r"(afr[mt][2]), "=r"(afr[mt][3])
                    : "r"(ad));
            }
            #pragma unroll
            for (int nt = 0; nt < 4; nt++) {
                int r = wn*32 + nt*8 + (lane & 7);
                int c = ks*16 + ((lane >> 3) & 1) * 8;
                uint32_t ad = smem_u32(&sB[r*72 + c]);
                asm volatile("ldmatrix.sync.aligned.m8n8.x2.shared.b16 {%0,%1}, [%2];"
                    : "=r"(bfr[nt][0]), "=r"(bfr[nt][1]) : "r"(ad));
            }
            #pragma unroll
            for (int mt = 0; mt < 4; mt++)
                #pragma unroll
                for (int nt = 0; nt < 4; nt++)
                    asm volatile("mma.sync.aligned.m16n8k16.row.col.f32.f16.f16.f32 "
                        "{%0,%1,%2,%3}, {%4,%5,%6,%7}, {%8,%9}, {%0,%1,%2,%3};"
                        : "+f"(acc[mt][nt][0]), "+f"(acc[mt][nt][1]),
                          "+f"(acc[mt][nt][2]), "+f"(acc[mt][nt][3])
                        : "r"(afr[mt][0]), "r"(afr[mt][1]), "r"(afr[mt][2]), "r"(afr[mt][3]),
                          "r"(bfr[nt][0]), "r"(bfr[nt][1]));
        }
        __syncthreads();
    }

    uint64_t pol = mk_policy();
    __half* out = g_K + (size_t)z * NN * NN;
    #pragma unroll
    for (int mt = 0; mt < 4; mt++)
        #pragma unroll
        for (int nt = 0; nt < 4; nt++) {
            int r = row0 + wm*64 + mt*16 + (lane >> 2);
            int c = col0 + wn*32 + nt*8 + (lane & 3) * 2;
            __half2 h01 = __floats2half2_rn(__expf(acc[mt][nt][0] - 1.f),
                                            __expf(acc[mt][nt][1] - 1.f));
            __half2 h23 = __floats2half2_rn(__expf(acc[mt][nt][2] - 1.f),
                                            __expf(acc[mt][nt][3] - 1.f));
            stg_el((uint32_t*)&out[(size_t)r      * NN + c], *(uint32_t*)&h01, pol);
            stg_el((uint32_t*)&out[(size_t)(r + 8)* NN + c], *(uint32_t*)&h23, pol);
        }
}

// ---------------- 3a) row pass: u = mu / (K v + stab) ----------------
// Finalizes v from the previous column sums; zeroes the parity buffer the
// upcoming column pass will accumulate into.
__global__ void __launch_bounds__(512) row_pass(int iter) {
    int cta  = blockIdx.x;              // 512 CTAs
    int plan = cta >> 8;
    int b    = (cta >> 6) & 3;
    int rblk = cta & 63;                // 64 blocks x 32 rows

    __shared__ __align__(16) float sv[NN];
    int tid = threadIdx.x;
    if (iter == 0) {
        sv[tid] = 1.f; sv[tid+512] = 1.f; sv[tid+1024] = 1.f; sv[tid+1536] = 1.f;
    } else {
        const float* c = g_c[(iter - 1) & 1][plan][b];
        float4 cc = *(const float4*)&c[tid * 4];
        float4 vv;
        vv.x = MU / (cc.x + STAB); vv.y = MU / (cc.y + STAB);
        vv.z = MU / (cc.z + STAB); vv.w = MU / (cc.w + STAB);
        *(float4*)&sv[tid * 4] = vv;
    }
    if (tid < 32) g_c[iter & 1][plan][b][rblk * 32 + tid] = 0.f;  // zero next accum slice
    __syncthreads();

    uint64_t pol = mk_policy();
    int warp = tid >> 5, lane = tid & 31;
    const __half* Kb = g_K + ((size_t)(plan * NB + b)) * NN * NN;
    int row0 = rblk * 32 + warp * 2;
    const uint4* kp0 = (const uint4*)(Kb + (size_t)row0 * NN);
    const uint4* kp1 = (const uint4*)(Kb + (size_t)(row0 + 1) * NN);

    // Front-batch all 16 loads (2 rows x 8) for MLP
    uint4 kv0[8], kv1[8];
    #pragma unroll
    for (int it = 0; it < 8; it++) kv0[it] = ldg_el(&kp0[it * 32 + lane], pol);
    #pragma unroll
    for (int it = 0; it < 8; it++) kv1[it] = ldg_el(&kp1[it * 32 + lane], pol);

    float s0 = 0.f, s1 = 0.f;
    #pragma unroll
    for (int it = 0; it < 8; it++) {
        int j = (it * 32 + lane) * 8;
        float4 w0 = *(const float4*)&sv[j];
        float4 w1 = *(const float4*)&sv[j + 4];
        {
            float2 f0 = __half22float2(*(__half2*)&kv0[it].x);
            float2 f1 = __half22float2(*(__half2*)&kv0[it].y);
            float2 f2 = __half22float2(*(__half2*)&kv0[it].z);
            float2 f3 = __half22float2(*(__half2*)&kv0[it].w);
            s0 += f0.x*w0.x + f0.y*w0.y + f1.x*w0.z + f1.y*w0.w
                + f2.x*w1.x + f2.y*w1.y + f3.x*w1.z + f3.y*w1.w;
        }
        {
            float2 f0 = __half22float2(*(__half2*)&kv1[it].x);
            float2 f1 = __half22float2(*(__half2*)&kv1[it].y);
            float2 f2 = __half22float2(*(__half2*)&kv1[it].z);
            float2 f3 = __half22float2(*(__half2*)&kv1[it].w);
            s1 += f0.x*w0.x + f0.y*w0.y + f1.x*w0.z + f1.y*w0.w
                + f2.x*w1.x + f2.y*w1.y + f3.x*w1.z + f3.y*w1.w;
        }
    }
    #pragma unroll
    for (int o = 16; o; o >>= 1) {
        s0 += __shfl_xor_sync(0xffffffffu, s0, o);
        s1 += __shfl_xor_sync(0xffffffffu, s1, o);
    }
    if (lane == 0) {
        g_u[plan][b][row0]     = MU / (s0 + STAB);
        g_u[plan][b][row0 + 1] = MU / (s1 + STAB);
    }
}

// ---------------- 3b) column pass: c = K^T u (partial, atomic) ----------------
// 16-row chunks, all 16 loads front-batched (MLP=16 per thread).
__global__ void __launch_bounds__(256, 2) col_pass(int iter) {
    int cta  = blockIdx.x;              // 1024 CTAs
    int plan = cta >> 9;
    int b    = (cta >> 7) & 3;
    int ch   = cta & 127;               // 128 chunks x 16 rows

    __shared__ float su[16];
    int tid = threadIdx.x;
    if (tid < 16) su[tid] = g_u[plan][b][ch * 16 + tid];
    __syncthreads();

    uint64_t pol = mk_policy();
    const uint4* kp = (const uint4*)(g_K + ((size_t)(plan * NB + b)) * NN * NN)
                    + (size_t)ch * 16 * 256 + tid;    // thread covers cols [tid*8, tid*8+8)

    uint4 kv[16];
    #pragma unroll
    for (int i = 0; i < 16; i++) kv[i] = ldg_el(kp + (size_t)i * 256, pol);

    float acc[8];
    #pragma unroll
    for (int k = 0; k < 8; k++) acc[k] = 0.f;

    #pragma unroll
    for (int i = 0; i < 16; i++) {
        float ui = su[i];
        float2 f0 = __half22float2(*(__half2*)&kv[i].x);
        float2 f1 = __half22float2(*(__half2*)&kv[i].y);
        float2 f2 = __half22float2(*(__half2*)&kv[i].z);
        float2 f3 = __half22float2(*(__half2*)&kv[i].w);
        acc[0] += f0.x*ui; acc[1] += f0.y*ui;
        acc[2] += f1.x*ui; acc[3] += f1.y*ui;
        acc[4] += f2.x*ui; acc[5] += f2.y*ui;
        acc[6] += f3.x*ui; acc[7] += f3.y*ui;
    }
    float* c = g_c[iter & 1][plan][b] + tid * 8;
    #pragma unroll
    for (int k = 0; k < 8; k++) atomicAdd(&c[k], acc[k]);
}

// ---------------- 4) loss = sum |u1 K1 v1 - u2 K2 v2| ----------------
__global__ void __launch_bounds__(512) loss_kernel() {
    int cta  = blockIdx.x;              // 128 CTAs: b(4) x rowblk(32 of 64 rows)
    int b    = cta >> 5;
    int rblk = cta & 31;
    const int LASTBUF = (ITERS - 1) & 1;

    __shared__ __align__(16) float sv[2][NN];
    int tid = threadIdx.x;
    {
        float4 c1 = *(const float4*)&g_c[LASTBUF][0][b][tid * 4];
        float4 c2 = *(const float4*)&g_c[LASTBUF][1][b][tid * 4];
        float4 v1, v2;
        v1.x = MU/(c1.x+STAB); v1.y = MU/(c1.y+STAB); v1.z = MU/(c1.z+STAB); v1.w = MU/(c1.w+STAB);
        v2.x = MU/(c2.x+STAB); v2.y = MU/(c2.y+STAB); v2.z = MU/(c2.z+STAB); v2.w = MU/(c2.w+STAB);
        *(float4*)&sv[0][tid * 4] = v1;
        *(float4*)&sv[1][tid * 4] = v2;
    }
    __syncthreads();

    int warp = tid >> 5, lane = tid & 31;
    const __half* K1 = g_K + (size_t)b        * NN * NN;
    const __half* K2 = g_K + (size_t)(NB + b) * NN * NN;
    float sum = 0.f;
    #pragma unroll
    for (int rr = 0; rr < 4; rr++) {
        int row = rblk * 64 + warp * 4 + rr;
        float u1 = g_u[0][b][row];
        float u2 = g_u[1][b][row];
        const uint4* k1p = (const uint4*)(K1 + (size_t)row * NN);
        const uint4* k2p = (const uint4*)(K2 + (size_t)row * NN);
        #pragma unroll
        for (int it = 0; it < 8; it++) {
            uint4 a = k1p[it * 32 + lane];
            uint4 d = k2p[it * 32 + lane];
            int j = (it * 32 + lane) * 8;
            float4 w0 = *(const float4*)&sv[0][j];
            float4 w1 = *(const float4*)&sv[0][j + 4];
            float4 x0 = *(const float4*)&sv[1][j];
            float4 x1 = *(const float4*)&sv[1][j + 4];
            float2 a0 = __half22float2(*(__half2*)&a.x);
            float2 a1 = __half22float2(*(__half2*)&a.y);
            float2 a2 = __half22float2(*(__half2*)&a.z);
            float2 a3 = __half22float2(*(__half2*)&a.w);
            float2 d0 = __half22float2(*(__half2*)&d.x);
            float2 d1 = __half22float2(*(__half2*)&d.y);
            float2 d2 = __half22float2(*(__half2*)&d.z);
            float2 d3 = __half22float2(*(__half2*)&d.w);
            sum += fabsf(u1*a0.x*w0.x - u2*d0.x*x0.x);
            sum += fabsf(u1*a0.y*w0.y - u2*d0.y*x0.y);
            sum += fabsf(u1*a1.x*w0.z - u2*d1.x*x0.z);
            sum += fabsf(u1*a1.y*w0.w - u2*d1.y*x0.w);
            sum += fabsf(u1*a2.x*w1.x - u2*d2.x*x1.x);
            sum += fabsf(u1*a2.y*w1.y - u2*d2.y*x1.y);
            sum += fabsf(u1*a3.x*w1.z - u2*d3.x*x1.z);
            sum += fabsf(u1*a3.y*w1.w - u2*d3.y*x1.w);
        }
    }
    #pragma unroll
    for (int o = 16; o; o >>= 1) sum += __shfl_xor_sync(0xffffffffu, sum, o);
    __shared__ float swp[16];
    if (lane == 0) swp[warp] = sum;
    __syncthreads();
    if (warp == 0) {
        float t = (lane < 16) ? swp[lane] : 0.f;
        #pragma unroll
        for (int o = 8; o; o >>= 1) t += __shfl_xor_sync(0xffffffffu, t, o);
        if (lane == 0) g_part[cta] = t;
    }
}

__global__ void final_kernel(float* __restrict__ out) {
    int tid = threadIdx.x;  // 128 threads
    float s = g_part[tid];
    #pragma unroll
    for (int o = 16; o; o >>= 1) s += __shfl_xor_sync(0xffffffffu, s, o);
    __shared__ float sw[4];
    if ((tid & 31) == 0) sw[tid >> 5] = s;
    __syncthreads();
    if (tid == 0) {
        float t = sw[0] + sw[1] + sw[2] + sw[3];
        out[0] = t * (1.0f / (4.0f * 2048.0f * 2048.0f));
    }
}

// ---------------- host entry ----------------
extern "C" void kernel_launch(void* const* d_in, const int* in_sizes, int n_in,
                              void* d_out, int out_size) {
    (void)in_sizes; (void)n_in; (void)out_size;
    const float* src = (const float*)d_in[0];
    const float* tgt = (const float*)d_in[1];
    const float* gen = (const float*)d_in[2];

    norm_kernel<<<3072, 256>>>(src, tgt, gen);

    dim3 gg(16, 16, 8);
    gemm_exp_kernel<<<gg, 256>>>();

    for (int it = 0; it < ITERS; it++) {
        row_pass<<<512, 512>>>(it);
        col_pass<<<1024, 256>>>(it);
    }

    loss_kernel<<<128, 512>>>();
    final_kernel<<<1, 128>>>((float*)d_out);
}

// round 7
// speedup vs baseline: 1.9701x; 1.9701x over previous
#include <cuda_runtime.h>
#include <cuda_fp16.h>
#include <cstdint>

// Problem constants
#define NB    4            // batches
#define NN    2048         // n = m per batch
#define DD    256          // feature dim
#define ITERS 50
#define MU    (1.0f/2048.0f)
#define STAB  1e-8f

// ---------------- device scratch (no allocations allowed) ----------------
static __device__ __align__(128) __half g_K[2ull * NB * NN * NN];   // 67 MB: [plan][b][i][j]
static __device__ __align__(16)  __half g_fn[3][8192ull * DD];      // normalized features
static __device__ float g_u[2][NB][NN];
static __device__ float g_c[2][2][NB][NN];                          // double-buffered column sums
static __device__ float g_part[256];

__device__ __forceinline__ uint32_t smem_u32(const void* p) {
    return (uint32_t)__cvta_generic_to_shared(p);
}

// ---------------- 1) row-normalize features, cast to fp16 ----------------
__global__ void __launch_bounds__(256) norm_kernel(const float* __restrict__ s0,
                                                   const float* __restrict__ s1,
                                                   const float* __restrict__ s2) {
    int gw   = (blockIdx.x * blockDim.x + threadIdx.x) >> 5;  // global warp = row id
    int lane = threadIdx.x & 31;
    int which = gw >> 13;           // 0..2
    int row   = gw & 8191;
    const float* in = which == 0 ? s0 : (which == 1 ? s1 : s2);
    const float4* p = (const float4*)(in + (size_t)row * DD);
    float4 a = p[lane];
    float4 b = p[lane + 32];
    float ss = a.x*a.x + a.y*a.y + a.z*a.z + a.w*a.w
             + b.x*b.x + b.y*b.y + b.z*b.z + b.w*b.w;
    #pragma unroll
    for (int o = 16; o; o >>= 1) ss += __shfl_xor_sync(0xffffffffu, ss, o);
    float inv = 1.0f / (sqrtf(ss) + STAB);
    __half2* out = (__half2*)&g_fn[which][(size_t)row * DD];
    out[lane*2    ] = __floats2half2_rn(a.x*inv, a.y*inv);
    out[lane*2 + 1] = __floats2half2_rn(a.z*inv, a.w*inv);
    out[64 + lane*2    ] = __floats2half2_rn(b.x*inv, b.y*inv);
    out[64 + lane*2 + 1] = __floats2half2_rn(b.z*inv, b.w*inv);
}

// ---------------- 2) K = exp(dot - 1), fp16 tensor-core GEMM ----------------
__global__ void __launch_bounds__(256) gemm_exp_kernel() {
    int z = blockIdx.z;                 // 0..7: plan*4 + b
    int plan = z >> 2, b = z & 3;
    const __half* A  = &g_fn[plan    ][(size_t)b * NN * DD];
    const __half* Bm = &g_fn[plan + 1][(size_t)b * NN * DD];
    int row0 = blockIdx.y * 128, col0 = blockIdx.x * 128;

    __shared__ __align__(16) __half sA[128 * 72];
    __shared__ __align__(16) __half sB[128 * 72];

    int tid = threadIdx.x, warp = tid >> 5, lane = tid & 31;
    int wm = warp & 1;
    int wn = warp >> 1;

    float acc[4][4][4];
    #pragma unroll
    for (int i = 0; i < 4; i++)
        #pragma unroll
        for (int j = 0; j < 4; j++)
            #pragma unroll
            for (int k = 0; k < 4; k++) acc[i][j][k] = 0.f;

    for (int kc = 0; kc < 4; kc++) {
        #pragma unroll
        for (int i = 0; i < 4; i++) {
            int idx = tid + i * 256;
            int r = idx >> 3, c8 = (idx & 7) * 8;
            *(uint4*)&sA[r*72 + c8] = *(const uint4*)&A [(size_t)(row0 + r)*DD + kc*64 + c8];
            *(uint4*)&sB[r*72 + c8] = *(const uint4*)&Bm[(size_t)(col0 + r)*DD + kc*64 + c8];
        }
        __syncthreads();
        #pragma unroll
        for (int ks = 0; ks < 4; ks++) {
            uint32_t afr[4][4], bfr[4][2];
            #pragma unroll
            for (int mt = 0; mt < 4; mt++) {
                int r = wm*64 + mt*16 + (lane & 15);
                int c = ks*16 + (lane >> 4) * 8;
                uint32_t ad = smem_u32(&sA[r*72 + c]);
                asm volatile("ldmatrix.sync.aligned.m8n8.x4.shared.b16 {%0,%1,%2,%3}, [%4];"
                    : "=r"(afr[mt][0]), "=r"(afr[mt][1]), "=r"(afr[mt][2]), "=r"(afr[mt][3])
                    : "r"(ad));
            }
            #pragma unroll
            for (int nt = 0; nt < 4; nt++) {
                int r = wn*32 + nt*8 + (lane & 7);
                int c = ks*16 + ((lane >> 3) & 1) * 8;
                uint32_t ad = smem_u32(&sB[r*72 + c]);
                asm volatile("ldmatrix.sync.aligned.m8n8.x2.shared.b16 {%0,%1}, [%2];"
                    : "=r"(bfr[nt][0]), "=r"(bfr[nt][1]) : "r"(ad));
            }
            #pragma unroll
            for (int mt = 0; mt < 4; mt++)
                #pragma unroll
                for (int nt = 0; nt < 4; nt++)
                    asm volatile("mma.sync.aligned.m16n8k16.row.col.f32.f16.f16.f32 "
                        "{%0,%1,%2,%3}, {%4,%5,%6,%7}, {%8,%9}, {%0,%1,%2,%3};"
                        : "+f"(acc[mt][nt][0]), "+f"(acc[mt][nt][1]),
                          "+f"(acc[mt][nt][2]), "+f"(acc[mt][nt][3])
                        : "r"(afr[mt][0]), "r"(afr[mt][1]), "r"(afr[mt][2]), "r"(afr[mt][3]),
                          "r"(bfr[nt][0]), "r"(bfr[nt][1]));
        }
        __syncthreads();
    }

    __half* out = g_K + (size_t)z * NN * NN;
    #pragma unroll
    for (int mt = 0; mt < 4; mt++)
        #pragma unroll
        for (int nt = 0; nt < 4; nt++) {
            int r = row0 + wm*64 + mt*16 + (lane >> 2);
            int c = col0 + wn*32 + nt*8 + (lane & 3) * 2;
            __half2 h01 = __floats2half2_rn(__expf(acc[mt][nt][0] - 1.f),
                                            __expf(acc[mt][nt][1] - 1.f));
            __half2 h23 = __floats2half2_rn(__expf(acc[mt][nt][2] - 1.f),
                                            __expf(acc[mt][nt][3] - 1.f));
            *(__half2*)&out[(size_t)r      * NN + c] = h01;
            *(__half2*)&out[(size_t)(r + 8)* NN + c] = h23;
        }
}

// ---------------- 3a) row pass: u = mu / (K v + stab) ----------------
// Also finalizes v from the previous column pass, and zeroes the parity
// buffer the upcoming column pass will accumulate into.  (Exact R2 version.)
__global__ void __launch_bounds__(512) row_pass(int iter) {
    int cta  = blockIdx.x;              // 512 CTAs
    int plan = cta >> 8;
    int b    = (cta >> 6) & 3;
    int rblk = cta & 63;                // 64 blocks x 32 rows

    __shared__ __align__(16) float sv[NN];
    int tid = threadIdx.x;
    if (iter == 0) {
        sv[tid] = 1.f; sv[tid+512] = 1.f; sv[tid+1024] = 1.f; sv[tid+1536] = 1.f;
    } else {
        const float* c = g_c[(iter - 1) & 1][plan][b];
        float4 cc = *(const float4*)&c[tid * 4];
        float4 vv;
        vv.x = MU / (cc.x + STAB); vv.y = MU / (cc.y + STAB);
        vv.z = MU / (cc.z + STAB); vv.w = MU / (cc.w + STAB);
        *(float4*)&sv[tid * 4] = vv;
    }
    if (tid < 32) g_c[iter & 1][plan][b][rblk * 32 + tid] = 0.f;  // zero next accum slice
    __syncthreads();

    int warp = tid >> 5, lane = tid & 31;
    const __half* Kb = g_K + ((size_t)(plan * NB + b)) * NN * NN;
    #pragma unroll
    for (int rr = 0; rr < 2; rr++) {
        int row = rblk * 32 + warp * 2 + rr;
        const uint4* kp = (const uint4*)(Kb + (size_t)row * NN);
        float sum = 0.f;
        #pragma unroll
        for (int it = 0; it < 8; it++) {
            uint4 kv = kp[it * 32 + lane];
            int j = (it * 32 + lane) * 8;
            float4 v0 = *(const float4*)&sv[j];
            float4 v1 = *(const float4*)&sv[j + 4];
            float2 f0 = __half22float2(*(__half2*)&kv.x);
            float2 f1 = __half22float2(*(__half2*)&kv.y);
            float2 f2 = __half22float2(*(__half2*)&kv.z);
            float2 f3 = __half22float2(*(__half2*)&kv.w);
            sum += f0.x*v0.x + f0.y*v0.y + f1.x*v0.z + f1.y*v0.w
                 + f2.x*v1.x + f2.y*v1.y + f3.x*v1.z + f3.y*v1.w;
        }
        #pragma unroll
        for (int o = 16; o; o >>= 1) sum += __shfl_xor_sync(0xffffffffu, sum, o);
        if (lane == 0) g_u[plan][b][row] = MU / (sum + STAB);
    }
}

// ---------------- 3b) column pass: c = K^T u (partial, atomic) ----------------
// 512 threads/CTA, thread owns 4 columns (one uint2 per row), 32-row loop
// fully unrolled with PLAIN loads so ptxas front-batches for MLP.
// Row stride in uint2 units: 2048 halves * 2 B / 8 B = 512.  (R5 bug: was 1024.)
__global__ void __launch_bounds__(512) col_pass(int iter) {
    int cta  = blockIdx.x;              // 512 CTAs
    int plan = cta >> 8;
    int b    = (cta >> 6) & 3;
    int ch   = cta & 63;                // 64 chunks x 32 rows

    __shared__ float su[32];
    int tid = threadIdx.x;
    if (tid < 32) su[tid] = g_u[plan][b][ch * 32 + tid];
    __syncthreads();

    const uint2* kp = (const uint2*)(g_K + ((size_t)(plan * NB + b)) * NN * NN
                    + (size_t)ch * 32 * NN) + tid;   // thread covers cols [tid*4, tid*4+4)

    float a0 = 0.f, a1 = 0.f, a2 = 0.f, a3 = 0.f;
    #pragma unroll
    for (int i = 0; i < 32; i++) {
        uint2 kv = kp[(size_t)i * 512];              // row stride = 2048 halves = 512 uint2
        float ui = su[i];
        float2 f0 = __half22float2(*(__half2*)&kv.x);
        float2 f1 = __half22float2(*(__half2*)&kv.y);
        a0 += f0.x * ui; a1 += f0.y * ui;
        a2 += f1.x * ui; a3 += f1.y * ui;
    }
    float* c = g_c[iter & 1][plan][b] + tid * 4;
    atomicAdd(&c[0], a0);
    atomicAdd(&c[1], a1);
    atomicAdd(&c[2], a2);
    atomicAdd(&c[3], a3);
}

// ---------------- 4) loss = sum |u1 K1 v1 - u2 K2 v2| ----------------
__global__ void __launch_bounds__(512) loss_kernel() {
    int cta  = blockIdx.x;              // 128 CTAs: b(4) x rowblk(32 of 64 rows)
    int b    = cta >> 5;
    int rblk = cta & 31;
    const int LASTBUF = (ITERS - 1) & 1;

    __shared__ __align__(16) float sv[2][NN];
    int tid = threadIdx.x;
    {
        float4 c1 = *(const float4*)&g_c[LASTBUF][0][b][tid * 4];
        float4 c2 = *(const float4*)&g_c[LASTBUF][1][b][tid * 4];
        float4 v1, v2;
        v1.x = MU/(c1.x+STAB); v1.y = MU/(c1.y+STAB); v1.z = MU/(c1.z+STAB); v1.w = MU/(c1.w+STAB);
        v2.x = MU/(c2.x+STAB); v2.y = MU/(c2.y+STAB); v2.z = MU/(c2.z+STAB); v2.w = MU/(c2.w+STAB);
        *(float4*)&sv[0][tid * 4] = v1;
        *(float4*)&sv[1][tid * 4] = v2;
    }
    __syncthreads();

    int warp = tid >> 5, lane = tid & 31;
    const __half* K1 = g_K + (size_t)b        * NN * NN;
    const __half* K2 = g_K + (size_t)(NB + b) * NN * NN;
    float sum = 0.f;
    #pragma unroll
    for (int rr = 0; rr < 4; rr++) {
        int row = rblk * 64 + warp * 4 + rr;
        float u1 = g_u[0][b][row];
        float u2 = g_u[1][b][row];
        const uint4* k1p = (const uint4*)(K1 + (size_t)row * NN);
        const uint4* k2p = (const uint4*)(K2 + (size_t)row * NN);
        #pragma unroll
        for (int it = 0; it < 8; it++) {
            uint4 a = k1p[it * 32 + lane];
            uint4 d = k2p[it * 32 + lane];
            int j = (it * 32 + lane) * 8;
            float4 w0 = *(const float4*)&sv[0][j];
            float4 w1 = *(const float4*)&sv[0][j + 4];
            float4 x0 = *(const float4*)&sv[1][j];
            float4 x1 = *(const float4*)&sv[1][j + 4];
            float2 a0 = __half22float2(*(__half2*)&a.x);
            float2 a1 = __half22float2(*(__half2*)&a.y);
            float2 a2 = __half22float2(*(__half2*)&a.z);
            float2 a3 = __half22float2(*(__half2*)&a.w);
            float2 d0 = __half22float2(*(__half2*)&d.x);
            float2 d1 = __half22float2(*(__half2*)&d.y);
            float2 d2 = __half22float2(*(__half2*)&d.z);
            float2 d3 = __half22float2(*(__half2*)&d.w);
            sum += fabsf(u1*a0.x*w0.x - u2*d0.x*x0.x);
            sum += fabsf(u1*a0.y*w0.y - u2*d0.y*x0.y);
            sum += fabsf(u1*a1.x*w0.z - u2*d1.x*x0.z);
            sum += fabsf(u1*a1.y*w0.w - u2*d1.y*x0.w);
            sum += fabsf(u1*a2.x*w1.x - u2*d2.x*x1.x);
            sum += fabsf(u1*a2.y*w1.y - u2*d2.y*x1.y);
            sum += fabsf(u1*a3.x*w1.z - u2*d3.x*x1.z);
            sum += fabsf(u1*a3.y*w1.w - u2*d3.y*x1.w);
        }
    }
    #pragma unroll
    for (int o = 16; o; o >>= 1) sum += __shfl_xor_sync(0xffffffffu, sum, o);
    __shared__ float swp[16];
    if (lane == 0) swp[warp] = sum;
    __syncthreads();
    if (warp == 0) {
        float t = (lane < 16) ? swp[lane] : 0.f;
        #pragma unroll
        for (int o = 8; o; o >>= 1) t += __shfl_xor_sync(0xffffffffu, t, o);
        if (lane == 0) g_part[cta] = t;
    }
}

__global__ void final_kernel(float* __restrict__ out) {
    int tid = threadIdx.x;  // 128 threads
    float s = g_part[tid];
    #pragma unroll
    for (int o = 16; o; o >>= 1) s += __shfl_xor_sync(0xffffffffu, s, o);
    __shared__ float sw[4];
    if ((tid & 31) == 0) sw[tid >> 5] = s;
    __syncthreads();
    if (tid == 0) {
        float t = sw[0] + sw[1] + sw[2] + sw[3];
        out[0] = t * (1.0f / (4.0f * 2048.0f * 2048.0f));
    }
}

// ---------------- host entry ----------------
extern "C" void kernel_launch(void* const* d_in, const int* in_sizes, int n_in,
                              void* d_out, int out_size) {
    (void)in_sizes; (void)n_in; (void)out_size;
    const float* src = (const float*)d_in[0];
    const float* tgt = (const float*)d_in[1];
    const float* gen = (const float*)d_in[2];

    norm_kernel<<<3072, 256>>>(src, tgt, gen);

    dim3 gg(16, 16, 8);
    gemm_exp_kernel<<<gg, 256>>>();

    for (int it = 0; it < ITERS; it++) {
        row_pass<<<512, 512>>>(it);
        col_pass<<<512, 512>>>(it);
    }

    loss_kernel<<<128, 512>>>();
    final_kernel<<<1, 128>>>((float*)d_out);
}

// round 8
// speedup vs baseline: 2.0742x; 1.0528x over previous
#include <cuda_runtime.h>
#include <cuda_fp16.h>
#include <cstdint>

// Problem constants
#define NB    4            // batches
#define NN    2048         // n = m per batch
#define DD    256          // feature dim
#define ITERS 50
#define MU    (1.0f/2048.0f)
#define STAB  1e-8f

// ---------------- device scratch (no allocations allowed) ----------------
static __device__ __align__(128) __half g_K[2ull * NB * NN * NN];   // 67 MB: [plan][b][i][j]
static __device__ __align__(16)  __half g_fn[3][8192ull * DD];      // normalized features
static __device__ float g_u[2][NB][NN];
static __device__ float g_c[3][2][NB][NN];                          // triple-buffered column sums
static __device__ float g_part[256];

__device__ __forceinline__ uint32_t smem_u32(const void* p) {
    return (uint32_t)__cvta_generic_to_shared(p);
}

// ---------------- 1) row-normalize features, cast to fp16; zero c[0] ----------------
__global__ void __launch_bounds__(256) norm_kernel(const float* __restrict__ s0,
                                                   const float* __restrict__ s1,
                                                   const float* __restrict__ s2) {
    int gt = blockIdx.x * blockDim.x + threadIdx.x;
    if (gt < 2 * NB * NN) ((float*)g_c[0])[gt] = 0.f;   // zero parity-0 accumulator

    int gw   = gt >> 5;             // global warp = row id
    int lane = threadIdx.x & 31;
    int which = gw >> 13;           // 0..2
    int row   = gw & 8191;
    const float* in = which == 0 ? s0 : (which == 1 ? s1 : s2);
    const float4* p = (const float4*)(in + (size_t)row * DD);
    float4 a = p[lane];
    float4 b = p[lane + 32];
    float ss = a.x*a.x + a.y*a.y + a.z*a.z + a.w*a.w
             + b.x*b.x + b.y*b.y + b.z*b.z + b.w*b.w;
    #pragma unroll
    for (int o = 16; o; o >>= 1) ss += __shfl_xor_sync(0xffffffffu, ss, o);
    float inv = 1.0f / (sqrtf(ss) + STAB);
    __half2* out = (__half2*)&g_fn[which][(size_t)row * DD];
    out[lane*2    ] = __floats2half2_rn(a.x*inv, a.y*inv);
    out[lane*2 + 1] = __floats2half2_rn(a.z*inv, a.w*inv);
    out[64 + lane*2    ] = __floats2half2_rn(b.x*inv, b.y*inv);
    out[64 + lane*2 + 1] = __floats2half2_rn(b.z*inv, b.w*inv);
}

// ---------------- 2) K = exp(dot - 1), fp16 tensor-core GEMM ----------------
__global__ void __launch_bounds__(256) gemm_exp_kernel() {
    int z = blockIdx.z;                 // 0..7: plan*4 + b
    int plan = z >> 2, b = z & 3;
    const __half* A  = &g_fn[plan    ][(size_t)b * NN * DD];
    const __half* Bm = &g_fn[plan + 1][(size_t)b * NN * DD];
    int row0 = blockIdx.y * 128, col0 = blockIdx.x * 128;

    __shared__ __align__(16) __half sA[128 * 72];
    __shared__ __align__(16) __half sB[128 * 72];

    int tid = threadIdx.x, warp = tid >> 5, lane = tid & 31;
    int wm = warp & 1;
    int wn = warp >> 1;

    float acc[4][4][4];
    #pragma unroll
    for (int i = 0; i < 4; i++)
        #pragma unroll
        for (int j = 0; j < 4; j++)
            #pragma unroll
            for (int k = 0; k < 4; k++) acc[i][j][k] = 0.f;

    for (int kc = 0; kc < 4; kc++) {
        #pragma unroll
        for (int i = 0; i < 4; i++) {
            int idx = tid + i * 256;
            int r = idx >> 3, c8 = (idx & 7) * 8;
            *(uint4*)&sA[r*72 + c8] = *(const uint4*)&A [(size_t)(row0 + r)*DD + kc*64 + c8];
            *(uint4*)&sB[r*72 + c8] = *(const uint4*)&Bm[(size_t)(col0 + r)*DD + kc*64 + c8];
        }
        __syncthreads();
        #pragma unroll
        for (int ks = 0; ks < 4; ks++) {
            uint32_t afr[4][4], bfr[4][2];
            #pragma unroll
            for (int mt = 0; mt < 4; mt++) {
                int r = wm*64 + mt*16 + (lane & 15);
                int c = ks*16 + (lane >> 4) * 8;
                uint32_t ad = smem_u32(&sA[r*72 + c]);
                asm volatile("ldmatrix.sync.aligned.m8n8.x4.shared.b16 {%0,%1,%2,%3}, [%4];"
                    : "=r"(afr[mt][0]), "=r"(afr[mt][1]), "=r"(afr[mt][2]), "=r"(afr[mt][3])
                    : "r"(ad));
            }
            #pragma unroll
            for (int nt = 0; nt < 4; nt++) {
                int r = wn*32 + nt*8 + (lane & 7);
                int c = ks*16 + ((lane >> 3) & 1) * 8;
                uint32_t ad = smem_u32(&sB[r*72 + c]);
                asm volatile("ldmatrix.sync.aligned.m8n8.x2.shared.b16 {%0,%1}, [%2];"
                    : "=r"(bfr[nt][0]), "=r"(bfr[nt][1]) : "r"(ad));
            }
            #pragma unroll
            for (int mt = 0; mt < 4; mt++)
                #pragma unroll
                for (int nt = 0; nt < 4; nt++)
                    asm volatile("mma.sync.aligned.m16n8k16.row.col.f32.f16.f16.f32 "
                        "{%0,%1,%2,%3}, {%4,%5,%6,%7}, {%8,%9}, {%0,%1,%2,%3};"
                        : "+f"(acc[mt][nt][0]), "+f"(acc[mt][nt][1]),
                          "+f"(acc[mt][nt][2]), "+f"(acc[mt][nt][3])
                        : "r"(afr[mt][0]), "r"(afr[mt][1]), "r"(afr[mt][2]), "r"(afr[mt][3]),
                          "r"(bfr[nt][0]), "r"(bfr[nt][1]));
        }
        __syncthreads();
    }

    __half* out = g_K + (size_t)z * NN * NN;
    #pragma unroll
    for (int mt = 0; mt < 4; mt++)
        #pragma unroll
        for (int nt = 0; nt < 4; nt++) {
            int r = row0 + wm*64 + mt*16 + (lane >> 2);
            int c = col0 + wn*32 + nt*8 + (lane & 3) * 2;
            __half2 h01 = __floats2half2_rn(__expf(acc[mt][nt][0] - 1.f),
                                            __expf(acc[mt][nt][1] - 1.f));
            __half2 h23 = __floats2half2_rn(__expf(acc[mt][nt][2] - 1.f),
                                            __expf(acc[mt][nt][3] - 1.f));
            *(__half2*)&out[(size_t)r      * NN + c] = h01;
            *(__half2*)&out[(size_t)(r + 8)* NN + c] = h23;
        }
}

// ---------------- 3) fused Sinkhorn iteration (no smem staging) ----------------
// CTA = (plan, b, 32-row chunk).  Triple-buffered c: read (iter-1)%3,
// write iter%3 (zeroed last iteration), zero (iter+1)%3.
//   Phase A: u = mu / (K v) for the CTA's 32 rows (row-major global reads)
//   Phase B: re-read the same 32x2048 block (L2-hot) and accumulate c += u_i K_ij
__global__ void __launch_bounds__(512) sink_iter(int iter) {
    int cta  = blockIdx.x;              // 512 CTAs
    int plan = cta >> 8;
    int b    = (cta >> 6) & 3;
    int ch   = cta & 63;                // 64 chunks x 32 rows

    __shared__ __align__(16) float sv[NN];
    __shared__ float su[32];
    int tid = threadIdx.x;

    // v from previous column sums
    if (iter == 0) {
        sv[tid] = 1.f; sv[tid+512] = 1.f; sv[tid+1024] = 1.f; sv[tid+1536] = 1.f;
    } else {
        const float* c = g_c[(iter + 2) % 3][plan][b];
        float4 cc = *(const float4*)&c[tid * 4];
        float4 vv;
        vv.x = MU / (cc.x + STAB); vv.y = MU / (cc.y + STAB);
        vv.z = MU / (cc.z + STAB); vv.w = MU / (cc.w + STAB);
        *(float4*)&sv[tid * 4] = vv;
    }
    // zero the buffer the NEXT iteration will accumulate into
    if (tid < 32) ((float*)g_c[(iter + 1) % 3])[cta * 32 + tid] = 0.f;
    __syncthreads();

    int warp = tid >> 5, lane = tid & 31;
    const __half* Kb = g_K + ((size_t)(plan * NB + b)) * NN * NN;

    // Phase A: warp handles 2 rows (row-major dot with v)
    #pragma unroll
    for (int rr = 0; rr < 2; rr++) {
        int row = ch * 32 + warp * 2 + rr;
        const uint4* kp = (const uint4*)(Kb + (size_t)row * NN);
        float sum = 0.f;
        #pragma unroll
        for (int it = 0; it < 8; it++) {
            uint4 kv = kp[it * 32 + lane];
            int j = (it * 32 + lane) * 8;
            float4 v0 = *(const float4*)&sv[j];
            float4 v1 = *(const float4*)&sv[j + 4];
            float2 f0 = __half22float2(*(__half2*)&kv.x);
            float2 f1 = __half22float2(*(__half2*)&kv.y);
            float2 f2 = __half22float2(*(__half2*)&kv.z);
            float2 f3 = __half22float2(*(__half2*)&kv.w);
            sum += f0.x*v0.x + f0.y*v0.y + f1.x*v0.z + f1.y*v0.w
                 + f2.x*v1.x + f2.y*v1.y + f3.x*v1.z + f3.y*v1.w;
        }
        #pragma unroll
        for (int o = 16; o; o >>= 1) sum += __shfl_xor_sync(0xffffffffu, sum, o);
        if (lane == 0) {
            float uu = MU / (sum + STAB);
            su[warp * 2 + rr] = uu;
            g_u[plan][b][row] = uu;                  // consumed by loss_kernel
        }
    }
    __syncthreads();

    // Phase B: thread owns 4 columns (uint2/row), re-reads the L2-hot block
    const uint2* kp = (const uint2*)(Kb + (size_t)ch * 32 * NN) + tid;
    float a0 = 0.f, a1 = 0.f, a2 = 0.f, a3 = 0.f;
    #pragma unroll
    for (int i = 0; i < 32; i++) {
        uint2 kv = kp[(size_t)i * 512];              // row stride = 2048 halves = 512 uint2
        float ui = su[i];
        float2 f0 = __half22float2(*(__half2*)&kv.x);
        float2 f1 = __half22float2(*(__half2*)&kv.y);
        a0 += f0.x * ui; a1 += f0.y * ui;
        a2 += f1.x * ui; a3 += f1.y * ui;
    }
    float* c = g_c[iter % 3][plan][b] + tid * 4;
    atomicAdd(&c[0], a0);
    atomicAdd(&c[1], a1);
    atomicAdd(&c[2], a2);
    atomicAdd(&c[3], a3);
}

// ---------------- 4) loss = sum |u1 K1 v1 - u2 K2 v2| ----------------
__global__ void __launch_bounds__(512) loss_kernel() {
    int cta  = blockIdx.x;              // 128 CTAs: b(4) x rowblk(32 of 64 rows)
    int b    = cta >> 5;
    int rblk = cta & 31;
    const int LASTBUF = (ITERS - 1) % 3;

    __shared__ __align__(16) float sv[2][NN];
    int tid = threadIdx.x;
    {
        float4 c1 = *(const float4*)&g_c[LASTBUF][0][b][tid * 4];
        float4 c2 = *(const float4*)&g_c[LASTBUF][1][b][tid * 4];
        float4 v1, v2;
        v1.x = MU/(c1.x+STAB); v1.y = MU/(c1.y+STAB); v1.z = MU/(c1.z+STAB); v1.w = MU/(c1.w+STAB);
        v2.x = MU/(c2.x+STAB); v2.y = MU/(c2.y+STAB); v2.z = MU/(c2.z+STAB); v2.w = MU/(c2.w+STAB);
        *(float4*)&sv[0][tid * 4] = v1;
        *(float4*)&sv[1][tid * 4] = v2;
    }
    __syncthreads();

    int warp = tid >> 5, lane = tid & 31;
    const __half* K1 = g_K + (size_t)b        * NN * NN;
    const __half* K2 = g_K + (size_t)(NB + b) * NN * NN;
    float sum = 0.f;
    #pragma unroll
    for (int rr = 0; rr < 4; rr++) {
        int row = rblk * 64 + warp * 4 + rr;
        float u1 = g_u[0][b][row];
        float u2 = g_u[1][b][row];
        const uint4* k1p = (const uint4*)(K1 + (size_t)row * NN);
        const uint4* k2p = (const uint4*)(K2 + (size_t)row * NN);
        #pragma unroll
        for (int it = 0; it < 8; it++) {
            uint4 a = k1p[it * 32 + lane];
            uint4 d = k2p[it * 32 + lane];
            int j = (it * 32 + lane) * 8;
            float4 w0 = *(const float4*)&sv[0][j];
            float4 w1 = *(const float4*)&sv[0][j + 4];
            float4 x0 = *(const float4*)&sv[1][j];
            float4 x1 = *(const float4*)&sv[1][j + 4];
            float2 a0 = __half22float2(*(__half2*)&a.x);
            float2 a1 = __half22float2(*(__half2*)&a.y);
            float2 a2 = __half22float2(*(__half2*)&a.z);
            float2 a3 = __half22float2(*(__half2*)&a.w);
            float2 d0 = __half22float2(*(__half2*)&d.x);
            float2 d1 = __half22float2(*(__half2*)&d.y);
            float2 d2 = __half22float2(*(__half2*)&d.z);
            float2 d3 = __half22float2(*(__half2*)&d.w);
            sum += fabsf(u1*a0.x*w0.x - u2*d0.x*x0.x);
            sum += fabsf(u1*a0.y*w0.y - u2*d0.y*x0.y);
            sum += fabsf(u1*a1.x*w0.z - u2*d1.x*x0.z);
            sum += fabsf(u1*a1.y*w0.w - u2*d1.y*x0.w);
            sum += fabsf(u1*a2.x*w1.x - u2*d2.x*x1.x);
            sum += fabsf(u1*a2.y*w1.y - u2*d2.y*x1.y);
            sum += fabsf(u1*a3.x*w1.z - u2*d3.x*x1.z);
            sum += fabsf(u1*a3.y*w1.w - u2*d3.y*x1.w);
        }
    }
    #pragma unroll
    for (int o = 16; o; o >>= 1) sum += __shfl_xor_sync(0xffffffffu, sum, o);
    __shared__ float swp[16];
    if (lane == 0) swp[warp] = sum;
    __syncthreads();
    if (warp == 0) {
        float t = (lane < 16) ? swp[lane] : 0.f;
        #pragma unroll
        for (int o = 8; o; o >>= 1) t += __shfl_xor_sync(0xffffffffu, t, o);
        if (lane == 0) g_part[cta] = t;
    }
}

__global__ void final_kernel(float* __restrict__ out) {
    int tid = threadIdx.x;  // 128 threads
    float s = g_part[tid];
    #pragma unroll
    for (int o = 16; o; o >>= 1) s += __shfl_xor_sync(0xffffffffu, s, o);
    __shared__ float sw[4];
    if ((tid & 31) == 0) sw[tid >> 5] = s;
    __syncthreads();
    if (tid == 0) {
        float t = sw[0] + sw[1] + sw[2] + sw[3];
        out[0] = t * (1.0f / (4.0f * 2048.0f * 2048.0f));
    }
}

// ---------------- host entry ----------------
extern "C" void kernel_launch(void* const* d_in, const int* in_sizes, int n_in,
                              void* d_out, int out_size) {
    (void)in_sizes; (void)n_in; (void)out_size;
    const float* src = (const float*)d_in[0];
    const float* tgt = (const float*)d_in[1];
    const float* gen = (const float*)d_in[2];

    norm_kernel<<<3072, 256>>>(src, tgt, gen);

    dim3 gg(16, 16, 8);
    gemm_exp_kernel<<<gg, 256>>>();

    for (int it = 0; it < ITERS; it++)
        sink_iter<<<512, 512>>>(it);

    loss_kernel<<<128, 512>>>();
    final_kernel<<<1, 128>>>((float*)d_out);
}

// round 9
// speedup vs baseline: 2.1619x; 1.0423x over previous
#include <cuda_runtime.h>
#include <cuda_fp16.h>
#include <cstdint>

// Problem constants
#define NB    4            // batches
#define NN    2048         // n = m per batch
#define DD    256          // feature dim
#define ITERS 50
#define MU    (1.0f/2048.0f)
#define STAB  1e-8f

// ---------------- device scratch (no allocations allowed) ----------------
static __device__ __align__(128) __half g_K[2ull * NB * NN * NN];   // 67 MB: [plan][b][i][j]
static __device__ __align__(16)  __half g_fn[3][8192ull * DD];      // normalized features
static __device__ float g_u[2][NB][NN];
static __device__ float g_c[3][2][NB][NN];                          // triple-buffered column sums
static __device__ float g_part[256];

__device__ __forceinline__ uint32_t smem_u32(const void* p) {
    return (uint32_t)__cvta_generic_to_shared(p);
}

// ---------------- 1) row-normalize features, cast to fp16; zero c[0] ----------------
__global__ void __launch_bounds__(256) norm_kernel(const float* __restrict__ s0,
                                                   const float* __restrict__ s1,
                                                   const float* __restrict__ s2) {
    int gt = blockIdx.x * blockDim.x + threadIdx.x;
    if (gt < 2 * NB * NN) ((float*)g_c[0])[gt] = 0.f;   // zero parity-0 accumulator

    int gw   = gt >> 5;             // global warp = row id
    int lane = threadIdx.x & 31;
    int which = gw >> 13;           // 0..2
    int row   = gw & 8191;
    const float* in = which == 0 ? s0 : (which == 1 ? s1 : s2);
    const float4* p = (const float4*)(in + (size_t)row * DD);
    float4 a = p[lane];
    float4 b = p[lane + 32];
    float ss = a.x*a.x + a.y*a.y + a.z*a.z + a.w*a.w
             + b.x*b.x + b.y*b.y + b.z*b.z + b.w*b.w;
    #pragma unroll
    for (int o = 16; o; o >>= 1) ss += __shfl_xor_sync(0xffffffffu, ss, o);
    float inv = 1.0f / (sqrtf(ss) + STAB);
    __half2* out = (__half2*)&g_fn[which][(size_t)row * DD];
    out[lane*2    ] = __floats2half2_rn(a.x*inv, a.y*inv);
    out[lane*2 + 1] = __floats2half2_rn(a.z*inv, a.w*inv);
    out[64 + lane*2    ] = __floats2half2_rn(b.x*inv, b.y*inv);
    out[64 + lane*2 + 1] = __floats2half2_rn(b.z*inv, b.w*inv);
}

// ---------------- 2) K = exp(dot - 1), fp16 tensor-core GEMM ----------------
__global__ void __launch_bounds__(256) gemm_exp_kernel() {
    int z = blockIdx.z;                 // 0..7: plan*4 + b
    int plan = z >> 2, b = z & 3;
    const __half* A  = &g_fn[plan    ][(size_t)b * NN * DD];
    const __half* Bm = &g_fn[plan + 1][(size_t)b * NN * DD];
    int row0 = blockIdx.y * 128, col0 = blockIdx.x * 128;

    __shared__ __align__(16) __half sA[128 * 72];
    __shared__ __align__(16) __half sB[128 * 72];

    int tid = threadIdx.x, warp = tid >> 5, lane = tid & 31;
    int wm = warp & 1;
    int wn = warp >> 1;

    float acc[4][4][4];
    #pragma unroll
    for (int i = 0; i < 4; i++)
        #pragma unroll
        for (int j = 0; j < 4; j++)
            #pragma unroll
            for (int k = 0; k < 4; k++) acc[i][j][k] = 0.f;

    for (int kc = 0; kc < 4; kc++) {
        #pragma unroll
        for (int i = 0; i < 4; i++) {
            int idx = tid + i * 256;
            int r = idx >> 3, c8 = (idx & 7) * 8;
            *(uint4*)&sA[r*72 + c8] = *(const uint4*)&A [(size_t)(row0 + r)*DD + kc*64 + c8];
            *(uint4*)&sB[r*72 + c8] = *(const uint4*)&Bm[(size_t)(col0 + r)*DD + kc*64 + c8];
        }
        __syncthreads();
        #pragma unroll
        for (int ks = 0; ks < 4; ks++) {
            uint32_t afr[4][4], bfr[4][2];
            #pragma unroll
            for (int mt = 0; mt < 4; mt++) {
                int r = wm*64 + mt*16 + (lane & 15);
                int c = ks*16 + (lane >> 4) * 8;
                uint32_t ad = smem_u32(&sA[r*72 + c]);
                asm volatile("ldmatrix.sync.aligned.m8n8.x4.shared.b16 {%0,%1,%2,%3}, [%4];"
                    : "=r"(afr[mt][0]), "=r"(afr[mt][1]), "=r"(afr[mt][2]), "=r"(afr[mt][3])
                    : "r"(ad));
            }
            #pragma unroll
            for (int nt = 0; nt < 4; nt++) {
                int r = wn*32 + nt*8 + (lane & 7);
                int c = ks*16 + ((lane >> 3) & 1) * 8;
                uint32_t ad = smem_u32(&sB[r*72 + c]);
                asm volatile("ldmatrix.sync.aligned.m8n8.x2.shared.b16 {%0,%1}, [%2];"
                    : "=r"(bfr[nt][0]), "=r"(bfr[nt][1]) : "r"(ad));
            }
            #pragma unroll
            for (int mt = 0; mt < 4; mt++)
                #pragma unroll
                for (int nt = 0; nt < 4; nt++)
                    asm volatile("mma.sync.aligned.m16n8k16.row.col.f32.f16.f16.f32 "
                        "{%0,%1,%2,%3}, {%4,%5,%6,%7}, {%8,%9}, {%0,%1,%2,%3};"
                        : "+f"(acc[mt][nt][0]), "+f"(acc[mt][nt][1]),
                          "+f"(acc[mt][nt][2]), "+f"(acc[mt][nt][3])
                        : "r"(afr[mt][0]), "r"(afr[mt][1]), "r"(afr[mt][2]), "r"(afr[mt][3]),
                          "r"(bfr[nt][0]), "r"(bfr[nt][1]));
        }
        __syncthreads();
    }

    __half* out = g_K + (size_t)z * NN * NN;
    #pragma unroll
    for (int mt = 0; mt < 4; mt++)
        #pragma unroll
        for (int nt = 0; nt < 4; nt++) {
            int r = row0 + wm*64 + mt*16 + (lane >> 2);
            int c = col0 + wn*32 + nt*8 + (lane & 3) * 2;
            __half2 h01 = __floats2half2_rn(__expf(acc[mt][nt][0] - 1.f),
                                            __expf(acc[mt][nt][1] - 1.f));
            __half2 h23 = __floats2half2_rn(__expf(acc[mt][nt][2] - 1.f),
                                            __expf(acc[mt][nt][3] - 1.f));
            *(__half2*)&out[(size_t)r      * NN + c] = h01;
            *(__half2*)&out[(size_t)(r + 8)* NN + c] = h23;
        }
}

// ---------------- 3) fused Sinkhorn iteration ----------------
// CTA = (plan, b, 32-row chunk).  Triple-buffered c: read (iter-1)%3,
// write iter%3 (zeroed last iteration), zero (iter+1)%3.
//   Phase A: u = mu / (K v) for the CTA's 32 rows (DRAM read)
//   Phase B: re-read the same 32x2048 block (L2-hot) and accumulate c += u_i K_ij
// __launch_bounds__(512, 2): cap regs at 64 so 2 CTAs/SM — R7 let regs hit 86
// (1 CTA/SM, occ 23.7%) and throttled the Phase A DRAM read to 2.2 TB/s.
__global__ void __launch_bounds__(512, 2) sink_iter(int iter) {
    int cta  = blockIdx.x;              // 512 CTAs
    int plan = cta >> 8;
    int b    = (cta >> 6) & 3;
    int ch   = cta & 63;                // 64 chunks x 32 rows

    __shared__ __align__(16) float sv[NN];
    __shared__ float su[32];
    int tid = threadIdx.x;

    // v from previous column sums
    if (iter == 0) {
        sv[tid] = 1.f; sv[tid+512] = 1.f; sv[tid+1024] = 1.f; sv[tid+1536] = 1.f;
    } else {
        const float* c = g_c[(iter + 2) % 3][plan][b];
        float4 cc = *(const float4*)&c[tid * 4];
        float4 vv;
        vv.x = MU / (cc.x + STAB); vv.y = MU / (cc.y + STAB);
        vv.z = MU / (cc.z + STAB); vv.w = MU / (cc.w + STAB);
        *(float4*)&sv[tid * 4] = vv;
    }
    // zero the buffer the NEXT iteration will accumulate into
    if (tid < 32) ((float*)g_c[(iter + 1) % 3])[cta * 32 + tid] = 0.f;
    __syncthreads();

    int warp = tid >> 5, lane = tid & 31;
    const __half* Kb = g_K + ((size_t)(plan * NB + b)) * NN * NN;

    // Phase A: warp handles 2 rows (row-major dot with v)
    #pragma unroll
    for (int rr = 0; rr < 2; rr++) {
        int row = ch * 32 + warp * 2 + rr;
        const uint4* kp = (const uint4*)(Kb + (size_t)row * NN);
        float sum = 0.f;
        #pragma unroll
        for (int it = 0; it < 8; it++) {
            uint4 kv = kp[it * 32 + lane];
            int j = (it * 32 + lane) * 8;
            float4 v0 = *(const float4*)&sv[j];
            float4 v1 = *(const float4*)&sv[j + 4];
            float2 f0 = __half22float2(*(__half2*)&kv.x);
            float2 f1 = __half22float2(*(__half2*)&kv.y);
            float2 f2 = __half22float2(*(__half2*)&kv.z);
            float2 f3 = __half22float2(*(__half2*)&kv.w);
            sum += f0.x*v0.x + f0.y*v0.y + f1.x*v0.z + f1.y*v0.w
                 + f2.x*v1.x + f2.y*v1.y + f3.x*v1.z + f3.y*v1.w;
        }
        #pragma unroll
        for (int o = 16; o; o >>= 1) sum += __shfl_xor_sync(0xffffffffu, sum, o);
        if (lane == 0) {
            float uu = MU / (sum + STAB);
            su[warp * 2 + rr] = uu;
            g_u[plan][b][row] = uu;                  // consumed by loss_kernel
        }
    }
    __syncthreads();

    // Phase B: thread owns 4 columns (uint2/row), re-reads the L2-hot block
    const uint2* kp = (const uint2*)(Kb + (size_t)ch * 32 * NN) + tid;
    float a0 = 0.f, a1 = 0.f, a2 = 0.f, a3 = 0.f;
    #pragma unroll
    for (int i = 0; i < 32; i++) {
        uint2 kv = kp[(size_t)i * 512];              // row stride = 2048 halves = 512 uint2
        float ui = su[i];
        float2 f0 = __half22float2(*(__half2*)&kv.x);
        float2 f1 = __half22float2(*(__half2*)&kv.y);
        a0 += f0.x * ui; a1 += f0.y * ui;
        a2 += f1.x * ui; a3 += f1.y * ui;
    }
    float* c = g_c[iter % 3][plan][b] + tid * 4;
    atomicAdd(&c[0], a0);
    atomicAdd(&c[1], a1);
    atomicAdd(&c[2], a2);
    atomicAdd(&c[3], a3);
}

// ---------------- 4) loss = sum |u1 K1 v1 - u2 K2 v2| ----------------
__global__ void __launch_bounds__(512) loss_kernel() {
    int cta  = blockIdx.x;              // 128 CTAs: b(4) x rowblk(32 of 64 rows)
    int b    = cta >> 5;
    int rblk = cta & 31;
    const int LASTBUF = (ITERS - 1) % 3;

    __shared__ __align__(16) float sv[2][NN];
    int tid = threadIdx.x;
    {
        float4 c1 = *(const float4*)&g_c[LASTBUF][0][b][tid * 4];
        float4 c2 = *(const float4*)&g_c[LASTBUF][1][b][tid * 4];
        float4 v1, v2;
        v1.x = MU/(c1.x+STAB); v1.y = MU/(c1.y+STAB); v1.z = MU/(c1.z+STAB); v1.w = MU/(c1.w+STAB);
        v2.x = MU/(c2.x+STAB); v2.y = MU/(c2.y+STAB); v2.z = MU/(c2.z+STAB); v2.w = MU/(c2.w+STAB);
        *(float4*)&sv[0][tid * 4] = v1;
        *(float4*)&sv[1][tid * 4] = v2;
    }
    __syncthreads();

    int warp = tid >> 5, lane = tid & 31;
    const __half* K1 = g_K + (size_t)b        * NN * NN;
    const __half* K2 = g_K + (size_t)(NB + b) * NN * NN;
    float sum = 0.f;
    #pragma unroll
    for (int rr = 0; rr < 4; rr++) {
        int row = rblk * 64 + warp * 4 + rr;
        float u1 = g_u[0][b][row];
        float u2 = g_u[1][b][row];
        const uint4* k1p = (const uint4*)(K1 + (size_t)row * NN);
        const uint4* k2p = (const uint4*)(K2 + (size_t)row * NN);
        #pragma unroll
        for (int it = 0; it < 8; it++) {
            uint4 a = k1p[it * 32 + lane];
            uint4 d = k2p[it * 32 + lane];
            int j = (it * 32 + lane) * 8;
            float4 w0 = *(const float4*)&sv[0][j];
            float4 w1 = *(const float4*)&sv[0][j + 4];
            float4 x0 = *(const float4*)&sv[1][j];
            float4 x1 = *(const float4*)&sv[1][j + 4];
            float2 a0 = __half22float2(*(__half2*)&a.x);
            float2 a1 = __half22float2(*(__half2*)&a.y);
            float2 a2 = __half22float2(*(__half2*)&a.z);
            float2 a3 = __half22float2(*(__half2*)&a.w);
            float2 d0 = __half22float2(*(__half2*)&d.x);
            float2 d1 = __half22float2(*(__half2*)&d.y);
            float2 d2 = __half22float2(*(__half2*)&d.z);
            float2 d3 = __half22float2(*(__half2*)&d.w);
            sum += fabsf(u1*a0.x*w0.x - u2*d0.x*x0.x);
            sum += fabsf(u1*a0.y*w0.y - u2*d0.y*x0.y);
            sum += fabsf(u1*a1.x*w0.z - u2*d1.x*x0.z);
            sum += fabsf(u1*a1.y*w0.w - u2*d1.y*x0.w);
            sum += fabsf(u1*a2.x*w1.x - u2*d2.x*x1.x);
            sum += fabsf(u1*a2.y*w1.y - u2*d2.y*x1.y);
            sum += fabsf(u1*a3.x*w1.z - u2*d3.x*x1.z);
            sum += fabsf(u1*a3.y*w1.w - u2*d3.y*x1.w);
        }
    }
    #pragma unroll
    for (int o = 16; o; o >>= 1) sum += __shfl_xor_sync(0xffffffffu, sum, o);
    __shared__ float swp[16];
    if (lane == 0) swp[warp] = sum;
    __syncthreads();
    if (warp == 0) {
        float t = (lane < 16) ? swp[lane] : 0.f;
        #pragma unroll
        for (int o = 8; o; o >>= 1) t += __shfl_xor_sync(0xffffffffu, t, o);
        if (lane == 0) g_part[cta] = t;
    }
}

__global__ void final_kernel(float* __restrict__ out) {
    int tid = threadIdx.x;  // 128 threads
    float s = g_part[tid];
    #pragma unroll
    for (int o = 16; o; o >>= 1) s += __shfl_xor_sync(0xffffffffu, s, o);
    __shared__ float sw[4];
    if ((tid & 31) == 0) sw[tid >> 5] = s;
    __syncthreads();
    if (tid == 0) {
        float t = sw[0] + sw[1] + sw[2] + sw[3];
        out[0] = t * (1.0f / (4.0f * 2048.0f * 2048.0f));
    }
}

// ---------------- host entry ----------------
extern "C" void kernel_launch(void* const* d_in, const int* in_sizes, int n_in,
                              void* d_out, int out_size) {
    (void)in_sizes; (void)n_in; (void)out_size;
    const float* src = (const float*)d_in[0];
    const float* tgt = (const float*)d_in[1];
    const float* gen = (const float*)d_in[2];

    norm_kernel<<<3072, 256>>>(src, tgt, gen);

    dim3 gg(16, 16, 8);
    gemm_exp_kernel<<<gg, 256>>>();

    for (int it = 0; it < ITERS; it++)
        sink_iter<<<512, 512>>>(it);

    loss_kernel<<<128, 512>>>();
    final_kernel<<<1, 128>>>((float*)d_out);
}